// round 14
// baseline (speedup 1.0000x reference)
#include <cuda_runtime.h>
#include <cuda_fp16.h>
#include <math.h>
#include <stdint.h>

#define Hh 256
#define N2d 32
#define Bb 8
#define Ll 4096

typedef unsigned long long ull;

// -------- scratch (no allocations allowed) --------
__device__ float g_lam_re[Hh*N2d], g_lam_im[Hh*N2d];
__device__ float g_c_re[Hh*N2d],   g_c_im[Hh*N2d];
__device__ __align__(16) __half g_Wh[2*Hh*Hh];
// Y natural layout: [b][h][l]. single fp16 (post-GELU activations).
__device__ __align__(16) __half g_Yh[(size_t)Bb*Hh*Ll];

__device__ __forceinline__ uint32_t smem_u32(const void* p) {
    uint32_t a;
    asm("{ .reg .u64 t; cvta.to.shared.u64 t, %1; cvt.u32.u64 %0, t; }" : "=r"(a) : "l"(p));
    return a;
}
__device__ __forceinline__ void ldsm4(uint32_t* r, uint32_t a) {
    asm volatile("ldmatrix.sync.aligned.m8n8.x4.shared.b16 {%0,%1,%2,%3}, [%4];"
                 : "=r"(r[0]), "=r"(r[1]), "=r"(r[2]), "=r"(r[3]) : "r"(a));
}
__device__ __forceinline__ void ldsm4t(uint32_t* r, uint32_t a) {
    asm volatile("ldmatrix.sync.aligned.m8n8.x4.trans.shared.b16 {%0,%1,%2,%3}, [%4];"
                 : "=r"(r[0]), "=r"(r[1]), "=r"(r[2]), "=r"(r[3]) : "r"(a));
}
__device__ __forceinline__ void mma16816(float* c, const uint32_t* a,
                                         uint32_t b0, uint32_t b1) {
    asm volatile(
        "mma.sync.aligned.m16n8k16.row.col.f32.f16.f16.f32 "
        "{%0,%1,%2,%3}, {%4,%5,%6,%7}, {%8,%9}, {%0,%1,%2,%3};"
        : "+f"(c[0]), "+f"(c[1]), "+f"(c[2]), "+f"(c[3])
        : "r"(a[0]), "r"(a[1]), "r"(a[2]), "r"(a[3]), "r"(b0), "r"(b1));
}
__device__ __forceinline__ void cpa16(uint32_t dst, const void* src) {
    asm volatile("cp.async.cg.shared.global [%0], [%1], 16;" :: "r"(dst), "l"(src));
}
// ---- packed f32x2 helpers ----
__device__ __forceinline__ ull pk2f(float lo, float hi) {
    ull r; asm("mov.b64 %0, {%1,%2};" : "=l"(r) : "f"(lo), "f"(hi)); return r;
}
__device__ __forceinline__ void upk2f(ull v, float& lo, float& hi) {
    asm("mov.b64 {%0,%1}, %2;" : "=f"(lo), "=f"(hi) : "l"(v));
}
__device__ __forceinline__ ull mul2(ull a, ull b) {
    ull d; asm("mul.rn.f32x2 %0, %1, %2;" : "=l"(d) : "l"(a), "l"(b)); return d;
}
__device__ __forceinline__ ull fma2(ull a, ull b, ull c) {
    ull d; asm("fma.rn.f32x2 %0, %1, %2, %3;" : "=l"(d) : "l"(a), "l"(b), "l"(c)); return d;
}
__device__ __forceinline__ ull add2(ull a, ull b) {
    ull d; asm("add.rn.f32x2 %0, %1, %2;" : "=l"(d) : "l"(a), "l"(b)); return d;
}

// ============================================================
// Kernel 1a: discretization  lambda = exp(dt*A),  c = 2*C*(lambda-1)/A
// ============================================================
__global__ void prep_kernel(const float* __restrict__ log_dt,
                            const float* __restrict__ C,
                            const float* __restrict__ log_A_real,
                            const float* __restrict__ A_imag) {
    int idx = blockIdx.x*blockDim.x + threadIdx.x;
    if (idx >= Hh*N2d) return;
    int h = idx / N2d;
    float dt  = expf(log_dt[h]);
    float Are = -expf(log_A_real[idx]);
    float Aim = A_imag[idx];
    float dr = Are*dt, di = Aim*dt;
    float er = expf(dr);
    float lr = er*cosf(di), li = er*sinf(di);
    float e1r = lr - 1.0f, e1i = li;
    float den = Are*Are + Aim*Aim;
    float ir =  Are/den, ii = -Aim/den;
    float tr = e1r*ir - e1i*ii;
    float ti = e1r*ii + e1i*ir;
    float Cr = C[2*idx], Ci = C[2*idx+1];
    g_lam_re[idx] = lr;  g_lam_im[idx] = li;
    g_c_re[idx] = 2.0f*(Cr*tr - Ci*ti);
    g_c_im[idx] = 2.0f*(Cr*ti + Ci*tr);
}

// ============================================================
// Kernel 1b: W -> fp16
// ============================================================
__global__ void wsplit_kernel(const float* __restrict__ W) {
    int i = blockIdx.x*blockDim.x + threadIdx.x;
    if (i >= 2*Hh*Hh) return;
    g_Wh[i] = __float2half(W[i]);
}

// ============================================================
// Kernel 2: diagonal-SSM scan, 2 channels/warp in f32x2 lanes.
// Critical-path restructure: each 8-step sub-block first computes
// all (Pr,Pi) = (CR2,CI2)*U in parallel (shfl latency pipelined),
// then runs the 8 chained recurrence steps (2 fma2/step chain).
// ============================================================
__global__ void __launch_bounds__(128) scan_kernel(const float* __restrict__ u,
                                                   const float* __restrict__ D) {
    __shared__ ull tile[4][32][33];
    int w    = threadIdx.x >> 5;
    int lane = threadIdx.x & 31;
    int wp   = blockIdx.x*4 + w;          // 0..1023 (channel pair)
    int ch0  = wp*2;
    int b    = ch0 >> 8;
    int h0   = ch0 & 255;
    const float* up0 = u + (size_t)(b*Hh + h0)*Ll;
    const float* up1 = up0 + Ll;
    __half* yh0 = g_Yh + (size_t)(b*Hh + h0)*Ll;
    __half* yh1 = yh0 + Ll;
    int ci0 = h0*N2d + lane, ci1 = ci0 + N2d;
    const ull LR2  = pk2f(g_lam_re[ci0],  g_lam_re[ci1]);
    const ull LI2  = pk2f(g_lam_im[ci0],  g_lam_im[ci1]);
    const ull NLI2 = pk2f(-g_lam_im[ci0], -g_lam_im[ci1]);
    const ull CR2  = pk2f(g_c_re[ci0],    g_c_re[ci1]);
    const ull CI2  = pk2f(g_c_im[ci0],    g_c_im[ci1]);
    float Dh0 = D[h0], Dh1 = D[h0+1];
    ull TRE = 0ULL, TIM = 0ULL;

    float uv0 = up0[lane], uv1 = up1[lane];   // block 0
    for (int ch = 0; ch < Ll/32; ++ch) {
        int nidx = (ch + 1 < Ll/32) ? (ch + 1)*32 : ch*32;
        float uv0n = up0[nidx + lane];
        float uv1n = up1[nidx + lane];
        #pragma unroll
        for (int sub = 0; sub < 4; ++sub) {
            // ---- phase A: parallel input terms (off the chain) ----
            ull Pr[8], Pi[8];
            #pragma unroll
            for (int j = 0; j < 8; ++j) {
                float u0 = __shfl_sync(0xffffffffu, uv0, sub*8 + j);
                float u1 = __shfl_sync(0xffffffffu, uv1, sub*8 + j);
                ull U2 = pk2f(u0, u1);
                Pr[j] = mul2(CR2, U2);
                Pi[j] = mul2(CI2, U2);
            }
            // ---- phase B: serial recurrence (2 fma2 chain/step) ----
            #pragma unroll
            for (int j = 0; j < 8; ++j) {
                ull nTRE = fma2(LR2, TRE, fma2(NLI2, TIM, Pr[j]));
                ull nTIM = fma2(LR2, TIM, fma2(LI2,  TRE, Pi[j]));
                TRE = nTRE; TIM = nTIM;
                tile[w][sub*8 + j][lane] = TRE;
            }
        }
        __syncwarp();
        // lane = output step: packed sum over 32 modes
        const ull* row = &tile[w][lane][0];
        ull s0 = 0ULL, s1 = 0ULL, s2 = 0ULL, s3 = 0ULL;
        #pragma unroll
        for (int j = 0; j < 32; j += 4) {
            s0 = add2(s0, row[j+0]);
            s1 = add2(s1, row[j+1]);
            s2 = add2(s2, row[j+2]);
            s3 = add2(s3, row[j+3]);
        }
        ull st = add2(add2(s0, s1), add2(s2, s3));
        float accA, accB; upk2f(st, accA, accB);
        float y0 = fmaf(Dh0, uv0, accA);
        float y1 = fmaf(Dh1, uv1, accB);
        float g0 = 0.5f*y0*(1.0f + erff(y0*0.70710678118654752f));
        float g1 = 0.5f*y1*(1.0f + erff(y1*0.70710678118654752f));
        yh0[ch*32 + lane] = __float2half(g0);
        yh1[ch*32 + lane] = __float2half(g1);
        uv0 = uv0n; uv1 = uv1n;
        __syncwarp();
    }
}

// ============================================================
// Kernel 3: HMMA.16816 fp16 GEMM + bias + GLU (R12, 50.3us).
// 512 threads, 128x128 tile, 3-stage cp.async.
// ============================================================
#define AROW 48
#define ABUF (128*AROW)
#define BROW 272
#define BBUF (16*BROW)
#define BOFF (2*ABUF)
#define STAGEB (2*ABUF + BBUF)
#define GEMM_SMEM (3*STAGEB)

__global__ void __launch_bounds__(512, 1) gemm_mma_kernel(const float* __restrict__ bias,
                                                          float* __restrict__ out) {
    extern __shared__ char smem[];
    const uint32_t sb = smem_u32(smem);

    const int tid  = threadIdx.x;
    const int lane = tid & 31;
    const int w    = tid >> 5;
    const int wm   = w >> 2;
    const int wn   = w & 3;
    const int l0 = blockIdx.x*128;
    const int h0 = blockIdx.y*128;
    const int b  = blockIdx.z;

    const int aarr = tid >> 8;
    const int arow = (tid & 255) >> 1, aseg = tid & 1;
    const __half* pA = g_Wh + (size_t)(aarr*Hh + h0 + arow)*Hh + aseg*8;
    const uint32_t aDst = (uint32_t)(aarr*ABUF + arow*AROW + aseg*16);
    const int brow = (tid >> 4) & 15, bch = tid & 15;
    const __half* pB = g_Yh + ((size_t)b*Hh + brow)*Ll + l0 + bch*8;
    const uint32_t bDst = (uint32_t)(BOFF + brow*BROW + bch*16);
    const bool doB = (tid < 256);

    const uint32_t a_off = (uint32_t)((lane & 15)*AROW + (lane >> 4)*16);
    const uint32_t b_off = (uint32_t)(((lane & 7) + ((lane >> 3) & 1)*8)*BROW
                                      + (lane >> 4)*16);

    float acc_a[2][4][4], acc_g[2][4][4];
    #pragma unroll
    for (int i = 0; i < 2; ++i)
        #pragma unroll
        for (int j = 0; j < 4; ++j)
            #pragma unroll
            for (int q = 0; q < 4; ++q) { acc_a[i][j][q] = 0.f; acc_g[i][j][q] = 0.f; }

    #pragma unroll
    for (int s = 0; s < 2; ++s) {
        uint32_t st = sb + (uint32_t)s*STAGEB;
        cpa16(st + aDst, pA + s*16);
        if (doB) cpa16(st + bDst, pB + (size_t)s*16*Ll);
        asm volatile("cp.async.commit_group;" ::: "memory");
    }

    int cur_s = 0;
    #pragma unroll 1
    for (int ks = 0; ks < 16; ++ks) {
        if (ks < 15) asm volatile("cp.async.wait_group 1;" ::: "memory");
        else         asm volatile("cp.async.wait_group 0;" ::: "memory");
        __syncthreads();
        if (ks + 2 < 16) {
            int s = ks + 2;
            int ss = cur_s + 2; if (ss >= 3) ss -= 3;
            uint32_t st = sb + (uint32_t)ss*STAGEB;
            cpa16(st + aDst, pA + s*16);
            if (doB) cpa16(st + bDst, pB + (size_t)s*16*Ll);
            asm volatile("cp.async.commit_group;" ::: "memory");
        }
        const uint32_t cur = sb + (uint32_t)cur_s*STAGEB;

        uint32_t bh[8];
        {
            uint32_t bas = cur + BOFF + b_off + (uint32_t)(wn*64);
            ldsm4t(&bh[0], bas);
            ldsm4t(&bh[4], bas + 32);
        }
        #pragma unroll
        for (int i = 0; i < 2; ++i) {
            uint32_t moff = (uint32_t)(wm*32 + i*16)*AROW + a_off;
            uint32_t aa[4], ag[4];
            ldsm4(aa, cur + 0*ABUF + moff);
            ldsm4(ag, cur + 1*ABUF + moff);
            #pragma unroll
            for (int j = 0; j < 4; ++j) {
                mma16816(acc_a[i][j], aa, bh[2*j], bh[2*j+1]);
                mma16816(acc_g[i][j], ag, bh[2*j], bh[2*j+1]);
            }
        }
        if (++cur_s == 3) cur_s = 0;
    }

    #pragma unroll
    for (int i = 0; i < 2; ++i) {
        int hr = h0 + wm*32 + i*16 + (lane >> 2);
        float ba0 = bias[hr],     bg0 = bias[Hh + hr];
        float ba1 = bias[hr + 8], bg1 = bias[Hh + hr + 8];
        #pragma unroll
        for (int j = 0; j < 4; ++j) {
            int col = l0 + wn*32 + j*8 + (lane & 3)*2;
            float a0 = acc_a[i][j][0] + ba0, g0 = acc_g[i][j][0] + bg0;
            float a1 = acc_a[i][j][1] + ba0, g1 = acc_g[i][j][1] + bg0;
            float a2 = acc_a[i][j][2] + ba1, g2 = acc_g[i][j][2] + bg1;
            float a3 = acc_a[i][j][3] + ba1, g3 = acc_g[i][j][3] + bg1;
            float2 v0 = make_float2(a0 / (1.0f + expf(-g0)),
                                    a1 / (1.0f + expf(-g1)));
            float2 v1 = make_float2(a2 / (1.0f + expf(-g2)),
                                    a3 / (1.0f + expf(-g3)));
            *(float2*)(out + ((size_t)b*Hh + hr)*Ll + col)     = v0;
            *(float2*)(out + ((size_t)b*Hh + hr + 8)*Ll + col) = v1;
        }
    }
}

// ============================================================
extern "C" void kernel_launch(void* const* d_in, const int* in_sizes, int n_in,
                              void* d_out, int out_size) {
    const float* u       = (const float*)d_in[0];
    const float* log_dt  = (const float*)d_in[1];
    const float* C       = (const float*)d_in[2];
    const float* lar     = (const float*)d_in[3];
    const float* aim     = (const float*)d_in[4];
    const float* D       = (const float*)d_in[5];
    const float* Wm      = (const float*)d_in[6];
    const float* bias    = (const float*)d_in[7];
    float* out = (float*)d_out;

    cudaFuncSetAttribute(gemm_mma_kernel,
                         cudaFuncAttributeMaxDynamicSharedMemorySize, GEMM_SMEM);

    prep_kernel<<<(Hh*N2d + 255)/256, 256>>>(log_dt, C, lar, aim);
    wsplit_kernel<<<(2*Hh*Hh + 255)/256, 256>>>(Wm);
    scan_kernel<<<(Bb*Hh/2)/4, 128>>>(u, D);
    dim3 grid(Ll/128, Hh/128, Bb);
    gemm_mma_kernel<<<grid, 512, GEMM_SMEM>>>(bias, out);
}

// round 15
// speedup vs baseline: 1.1965x; 1.1965x over previous
#include <cuda_runtime.h>
#include <cuda_fp16.h>
#include <math.h>
#include <stdint.h>

#define Hh 256
#define N2d 32
#define Bb 8
#define Ll 4096
#define LC 64
#define NC 64          // chunks per (b,h)
#define NCOL 512       // Bb*NC

// -------- scratch (no allocations allowed) --------
__device__ float g_lam_re[Hh*N2d], g_lam_im[Hh*N2d];
__device__ float g_c_re[Hh*N2d],   g_c_im[Hh*N2d];
__device__ float g_lamK_re[Hh*N2d], g_lamK_im[Hh*N2d];          // lambda^64
__device__ __align__(16) __half g_u16[(size_t)Bb*Hh*Ll];        // u in fp16
__device__ __align__(16) __half g_VT[Hh*64*64];                 // VT[h][k=j][n'] (s GEMM B)
__device__ __align__(16) __half g_KET[(size_t)Hh*128*64];       // [K|E]^T[h][k][i]
__device__ float g_ST[(size_t)Hh*NCOL*64];                      // S^T[h][col][n']
__device__ __align__(16) __half g_TinitT[(size_t)Hh*NCOL*64];   // Tinit^T[h][col][n']
__device__ __align__(16) __half g_Wh[2*Hh*Hh];
__device__ __align__(16) __half g_Yh[(size_t)Bb*Hh*Ll];         // post-GELU activations

__device__ __forceinline__ uint32_t smem_u32(const void* p) {
    uint32_t a;
    asm("{ .reg .u64 t; cvta.to.shared.u64 t, %1; cvt.u32.u64 %0, t; }" : "=r"(a) : "l"(p));
    return a;
}
__device__ __forceinline__ void ldsm4(uint32_t* r, uint32_t a) {
    asm volatile("ldmatrix.sync.aligned.m8n8.x4.shared.b16 {%0,%1,%2,%3}, [%4];"
                 : "=r"(r[0]), "=r"(r[1]), "=r"(r[2]), "=r"(r[3]) : "r"(a));
}
__device__ __forceinline__ void ldsm4t(uint32_t* r, uint32_t a) {
    asm volatile("ldmatrix.sync.aligned.m8n8.x4.trans.shared.b16 {%0,%1,%2,%3}, [%4];"
                 : "=r"(r[0]), "=r"(r[1]), "=r"(r[2]), "=r"(r[3]) : "r"(a));
}
__device__ __forceinline__ void mma16816(float* c, const uint32_t* a,
                                         uint32_t b0, uint32_t b1) {
    asm volatile(
        "mma.sync.aligned.m16n8k16.row.col.f32.f16.f16.f32 "
        "{%0,%1,%2,%3}, {%4,%5,%6,%7}, {%8,%9}, {%0,%1,%2,%3};"
        : "+f"(c[0]), "+f"(c[1]), "+f"(c[2]), "+f"(c[3])
        : "r"(a[0]), "r"(a[1]), "r"(a[2]), "r"(a[3]), "r"(b0), "r"(b1));
}
__device__ __forceinline__ void cpa16(uint32_t dst, const void* src) {
    asm volatile("cp.async.cg.shared.global [%0], [%1], 16;" :: "r"(dst), "l"(src));
}
__device__ __forceinline__ void cp_commit_wait0() {
    asm volatile("cp.async.commit_group;" ::: "memory");
    asm volatile("cp.async.wait_group 0;" ::: "memory");
}
__device__ __forceinline__ float gelu_exact(float y) {
    return 0.5f*y*(1.0f + erff(y*0.70710678118654752f));
}

// ============================================================
// 1a: discretization  lambda = exp(dt*A),  c = 2*C*(lambda-1)/A
// ============================================================
__global__ void prep_kernel(const float* __restrict__ log_dt,
                            const float* __restrict__ C,
                            const float* __restrict__ log_A_real,
                            const float* __restrict__ A_imag) {
    int idx = blockIdx.x*blockDim.x + threadIdx.x;
    if (idx >= Hh*N2d) return;
    int h = idx / N2d;
    float dt  = expf(log_dt[h]);
    float Are = -expf(log_A_real[idx]);
    float Aim = A_imag[idx];
    float dr = Are*dt, di = Aim*dt;
    float er = expf(dr);
    float lr = er*cosf(di), li = er*sinf(di);
    float e1r = lr - 1.0f, e1i = li;
    float den = Are*Are + Aim*Aim;
    float ir =  Are/den, ii = -Aim/den;
    float tr = e1r*ir - e1i*ii;
    float ti = e1r*ii + e1i*ir;
    float Cr = C[2*idx], Ci = C[2*idx+1];
    g_lam_re[idx] = lr;  g_lam_im[idx] = li;
    g_c_re[idx] = 2.0f*(Cr*tr - Ci*ti);
    g_c_im[idx] = 2.0f*(Cr*ti + Ci*tr);
}

// ============================================================
// 1b: W -> fp16
// ============================================================
__global__ void wsplit_kernel(const float* __restrict__ W) {
    int i = blockIdx.x*blockDim.x + threadIdx.x;
    if (i >= 2*Hh*Hh) return;
    g_Wh[i] = __float2half(W[i]);
}

// ============================================================
// 1c: u -> fp16
// ============================================================
__global__ void ucvt_kernel(const float* __restrict__ u) {
    int i = blockIdx.x*blockDim.x + threadIdx.x;     // per float4
    float4 v = ((const float4*)u)[i];
    ((__half2*)g_u16)[i*2]   = __floats2half2_rn(v.x, v.y);
    ((__half2*)g_u16)[i*2+1] = __floats2half2_rn(v.z, v.w);
}

// ============================================================
// 1d: powers — build VT, KET (K Toeplitz + E carry), lamK.
// warp = h, lane = mode n.
//   VT[k=j][n]     = Re(c lam^{63-j}),  VT[k][32+n] = Im(...)
//   KET[k<64][i]   = kk[i-k] (i>=k) else 0,  kk[d] = sum_n Re(c lam^d)
//   KET[64+n][i]   = Re(lam^{i+1}),  KET[96+n][i] = -Im(lam^{i+1})
// ============================================================
__global__ void __launch_bounds__(256) powers_kernel() {
    __shared__ float kk[8][64];
    int w = threadIdx.x >> 5, lane = threadIdx.x & 31;
    int h = blockIdx.x*8 + w;
    int ci = h*N2d + lane;
    float lr = g_lam_re[ci], li = g_lam_im[ci];
    float cr = g_c_re[ci],   cim = g_c_im[ci];
    float pr = 1.0f, pi = 0.0f;
    __half* vt  = g_VT  + (size_t)h*4096;
    __half* ket = g_KET + (size_t)h*8192;
    #pragma unroll 1
    for (int d = 0; d < 64; ++d) {
        float re = cr*pr - cim*pi;
        float im = cr*pi + cim*pr;
        vt[(63-d)*64 + lane]      = __float2half(re);
        vt[(63-d)*64 + 32 + lane] = __float2half(im);
        float s = re;
        #pragma unroll
        for (int o = 16; o > 0; o >>= 1) s += __shfl_xor_sync(0xffffffffu, s, o);
        if (lane == 0) kk[w][d] = s;
        float nr = pr*lr - pi*li, ni = pr*li + pi*lr;   // p *= lam
        pr = nr; pi = ni;
        ket[(64+lane)*64 + d] = __float2half(pr);
        ket[(96+lane)*64 + d] = __float2half(-pi);
    }
    g_lamK_re[ci] = pr; g_lamK_im[ci] = pi;             // lam^64
    __syncwarp();
    for (int t = lane; t < 4096; t += 32) {
        int k = t >> 6, i = t & 63;
        ket[k*64 + i] = (i >= k) ? __float2half(kk[w][i-k]) : __float2half(0.0f);
    }
}

// ============================================================
// 2: GEMM-S:  S^T[col][n'] = sum_j u16[col][j] * VT[j][n']
// CTA: M=128 cols, N=64, K=64. 8 warps = 4(M) x 2(N), 32x32.
// ============================================================
#define SAROW 144
#define SBROW 144
__global__ void __launch_bounds__(256) gemmS_kernel() {
    __shared__ char smem[128*SAROW + 64*SBROW];
    uint32_t sb  = smem_u32(smem);
    uint32_t sbB = sb + 128*SAROW;
    int tid = threadIdx.x, lane = tid & 31, w = tid >> 5;
    int wm = w >> 1, wn = w & 1;
    int h = blockIdx.y;
    int gm0 = blockIdx.x*128;
    // A: 128 rows x 128B
    #pragma unroll
    for (int t = 0; t < 4; ++t) {
        int id = tid + t*256;
        int row = id >> 3, seg = id & 7;
        int gm = gm0 + row, b = gm >> 6, cc = gm & 63;
        cpa16(sb + row*SAROW + seg*16,
              g_u16 + ((size_t)(b*Hh + h)*Ll + cc*64) + seg*8);
    }
    // B: 64 rows x 128B
    #pragma unroll
    for (int t = 0; t < 2; ++t) {
        int id = tid + t*256;
        int row = id >> 3, seg = id & 7;
        cpa16(sbB + row*SBROW + seg*16, g_VT + (size_t)h*4096 + row*64 + seg*8);
    }
    cp_commit_wait0();
    __syncthreads();
    const uint32_t a_off = (lane & 15)*SAROW + (lane >> 4)*16;
    const uint32_t b_off = ((lane & 7) + ((lane >> 3) & 1)*8)*SBROW + (lane >> 4)*16;
    float acc[2][4][4];
    #pragma unroll
    for (int i = 0; i < 2; ++i)
        #pragma unroll
        for (int j = 0; j < 4; ++j)
            #pragma unroll
            for (int q = 0; q < 4; ++q) acc[i][j][q] = 0.f;
    #pragma unroll
    for (int ks = 0; ks < 4; ++ks) {
        uint32_t bh[8];
        uint32_t bas = sbB + (uint32_t)(ks*16)*SBROW + b_off + (uint32_t)(wn*64);
        ldsm4t(&bh[0], bas);
        ldsm4t(&bh[4], bas + 32);
        #pragma unroll
        for (int i = 0; i < 2; ++i) {
            uint32_t aa[4];
            ldsm4(aa, sb + (uint32_t)(wm*32 + i*16)*SAROW + (uint32_t)(ks*32) + a_off);
            #pragma unroll
            for (int j = 0; j < 4; ++j)
                mma16816(acc[i][j], aa, bh[2*j], bh[2*j+1]);
        }
    }
    float* stp = g_ST + ((size_t)h*NCOL + gm0)*64;
    #pragma unroll
    for (int i = 0; i < 2; ++i) {
        int rm = wm*32 + i*16 + (lane >> 2);
        #pragma unroll
        for (int j = 0; j < 4; ++j) {
            int cn = wn*32 + j*8 + (lane & 3)*2;
            *(float2*)(stp + (size_t)rm*64 + cn)     = make_float2(acc[i][j][0], acc[i][j][1]);
            *(float2*)(stp + (size_t)(rm+8)*64 + cn) = make_float2(acc[i][j][2], acc[i][j][3]);
        }
    }
}

// ============================================================
// 3: chain — serial state propagation across 64 chunks.
// warp = (b,h), lane = mode. Write state BEFORE update (Tinit(c)
// = end of chunk c-1; c=0 gets zeros).
// ============================================================
__global__ void __launch_bounds__(256) chain_kernel() {
    int w = threadIdx.x >> 5, lane = threadIdx.x & 31;
    int wid = blockIdx.x*8 + w;           // 0..2047
    int b = wid >> 8, h = wid & 255;
    int ci = h*N2d + lane;
    float kr = g_lamK_re[ci], ki = g_lamK_im[ci];
    float tr = 0.f, ti = 0.f;
    const float* st = g_ST     + ((size_t)h*NCOL + b*64)*64;
    __half*      tt = g_TinitT + ((size_t)h*NCOL + b*64)*64;
    #pragma unroll 1
    for (int c = 0; c < 64; ++c) {
        tt[(size_t)c*64 + lane]      = __float2half(tr);
        tt[(size_t)c*64 + 32 + lane] = __float2half(ti);
        float sre = st[(size_t)c*64 + lane];
        float sim = st[(size_t)c*64 + 32 + lane];
        float nr = fmaf(kr, tr, fmaf(-ki, ti, sre));
        float ni = fmaf(kr, ti, fmaf( ki, tr, sim));
        tr = nr; ti = ni;
    }
}

// ============================================================
// 4: GEMM-Y:  y^T[col][i] = sum_k [u16|Tinit][col][k] * KET[k][i]
// + skip (D*u, fp32 u) + exact GELU -> g_Yh fp16.
// CTA: M=128 cols, N=64, K=128. 8 warps = 4(M) x 2(N), 32x32.
// ============================================================
#define YAROW 272
#define YBROW 144
#define YSMEM (128*YAROW + 128*YBROW)   // 53248
__global__ void __launch_bounds__(256) gemmY_kernel(const float* __restrict__ u,
                                                    const float* __restrict__ D) {
    extern __shared__ char ysmem[];
    uint32_t sb  = smem_u32(ysmem);
    uint32_t sbB = sb + 128*YAROW;
    int tid = threadIdx.x, lane = tid & 31, w = tid >> 5;
    int wm = w >> 1, wn = w & 1;
    int h = blockIdx.y;
    int gm0 = blockIdx.x*128;
    float Dh = D[h];
    // A: 128 rows x 256B  (first 128B = u16 col, second = TinitT col)
    #pragma unroll
    for (int t = 0; t < 8; ++t) {
        int id = tid + t*256;
        int row = id >> 4, seg = id & 15;
        int gm = gm0 + row, b = gm >> 6, cc = gm & 63;
        const __half* src = (seg < 8)
            ? g_u16 + ((size_t)(b*Hh + h)*Ll + cc*64) + seg*8
            : g_TinitT + ((size_t)h*NCOL + gm)*64 + (seg-8)*8;
        cpa16(sb + row*YAROW + seg*16, src);
    }
    // B: KET 128 rows x 128B
    #pragma unroll
    for (int t = 0; t < 4; ++t) {
        int id = tid + t*256;
        int row = id >> 3, seg = id & 7;
        cpa16(sbB + row*YBROW + seg*16, g_KET + (size_t)h*8192 + row*64 + seg*8);
    }
    cp_commit_wait0();
    __syncthreads();
    const uint32_t a_off = (lane & 15)*YAROW + (lane >> 4)*16;
    const uint32_t b_off = ((lane & 7) + ((lane >> 3) & 1)*8)*YBROW + (lane >> 4)*16;
    float acc[2][4][4];
    #pragma unroll
    for (int i = 0; i < 2; ++i)
        #pragma unroll
        for (int j = 0; j < 4; ++j)
            #pragma unroll
            for (int q = 0; q < 4; ++q) acc[i][j][q] = 0.f;
    #pragma unroll
    for (int ks = 0; ks < 8; ++ks) {
        uint32_t bh[8];
        uint32_t bas = sbB + (uint32_t)(ks*16)*YBROW + b_off + (uint32_t)(wn*64);
        ldsm4t(&bh[0], bas);
        ldsm4t(&bh[4], bas + 32);
        #pragma unroll
        for (int i = 0; i < 2; ++i) {
            uint32_t aa[4];
            ldsm4(aa, sb + (uint32_t)(wm*32 + i*16)*YAROW + (uint32_t)(ks*32) + a_off);
            #pragma unroll
            for (int j = 0; j < 4; ++j)
                mma16816(acc[i][j], aa, bh[2*j], bh[2*j+1]);
        }
    }
    // epilogue: skip + GELU -> g_Yh
    #pragma unroll
    for (int i = 0; i < 2; ++i) {
        #pragma unroll
        for (int qq = 0; qq < 2; ++qq) {
            int rm = wm*32 + i*16 + (lane >> 2) + qq*8;
            int gm = gm0 + rm, b = gm >> 6, cc = gm & 63;
            size_t rowbase = (size_t)(b*Hh + h)*Ll + cc*64;
            #pragma unroll
            for (int j = 0; j < 4; ++j) {
                int cn = wn*32 + j*8 + (lane & 3)*2;
                float a0 = acc[i][j][qq*2 + 0];
                float a1 = acc[i][j][qq*2 + 1];
                float2 uu = *(const float2*)(u + rowbase + cn);
                float y0 = a0 + Dh*uu.x;
                float y1 = a1 + Dh*uu.y;
                *(__half2*)(g_Yh + rowbase + cn) =
                    __floats2half2_rn(gelu_exact(y0), gelu_exact(y1));
            }
        }
    }
}

// ============================================================
// 5: HMMA fp16 W-GEMM + bias + GLU (R12, 50us, unchanged).
// ============================================================
#define AROW 48
#define ABUF (128*AROW)
#define BROW 272
#define BBUF (16*BROW)
#define BOFF (2*ABUF)
#define STAGEB (2*ABUF + BBUF)
#define GEMM_SMEM (3*STAGEB)

__global__ void __launch_bounds__(512, 1) gemm_mma_kernel(const float* __restrict__ bias,
                                                          float* __restrict__ out) {
    extern __shared__ char smem[];
    const uint32_t sb = smem_u32(smem);
    const int tid  = threadIdx.x;
    const int lane = tid & 31;
    const int w    = tid >> 5;
    const int wm   = w >> 2;
    const int wn   = w & 3;
    const int l0 = blockIdx.x*128;
    const int h0 = blockIdx.y*128;
    const int b  = blockIdx.z;

    const int aarr = tid >> 8;
    const int arow = (tid & 255) >> 1, aseg = tid & 1;
    const __half* pA = g_Wh + (size_t)(aarr*Hh + h0 + arow)*Hh + aseg*8;
    const uint32_t aDst = (uint32_t)(aarr*ABUF + arow*AROW + aseg*16);
    const int brow = (tid >> 4) & 15, bch = tid & 15;
    const __half* pB = g_Yh + ((size_t)b*Hh + brow)*Ll + l0 + bch*8;
    const uint32_t bDst = (uint32_t)(BOFF + brow*BROW + bch*16);
    const bool doB = (tid < 256);

    const uint32_t a_off = (uint32_t)((lane & 15)*AROW + (lane >> 4)*16);
    const uint32_t b_off = (uint32_t)(((lane & 7) + ((lane >> 3) & 1)*8)*BROW
                                      + (lane >> 4)*16);

    float acc_a[2][4][4], acc_g[2][4][4];
    #pragma unroll
    for (int i = 0; i < 2; ++i)
        #pragma unroll
        for (int j = 0; j < 4; ++j)
            #pragma unroll
            for (int q = 0; q < 4; ++q) { acc_a[i][j][q] = 0.f; acc_g[i][j][q] = 0.f; }

    #pragma unroll
    for (int s = 0; s < 2; ++s) {
        uint32_t st = sb + (uint32_t)s*STAGEB;
        cpa16(st + aDst, pA + s*16);
        if (doB) cpa16(st + bDst, pB + (size_t)s*16*Ll);
        asm volatile("cp.async.commit_group;" ::: "memory");
    }

    int cur_s = 0;
    #pragma unroll 1
    for (int ks = 0; ks < 16; ++ks) {
        if (ks < 15) asm volatile("cp.async.wait_group 1;" ::: "memory");
        else         asm volatile("cp.async.wait_group 0;" ::: "memory");
        __syncthreads();
        if (ks + 2 < 16) {
            int s = ks + 2;
            int ss = cur_s + 2; if (ss >= 3) ss -= 3;
            uint32_t st = sb + (uint32_t)ss*STAGEB;
            cpa16(st + aDst, pA + s*16);
            if (doB) cpa16(st + bDst, pB + (size_t)s*16*Ll);
            asm volatile("cp.async.commit_group;" ::: "memory");
        }
        const uint32_t cur = sb + (uint32_t)cur_s*STAGEB;
        uint32_t bh[8];
        {
            uint32_t bas = cur + BOFF + b_off + (uint32_t)(wn*64);
            ldsm4t(&bh[0], bas);
            ldsm4t(&bh[4], bas + 32);
        }
        #pragma unroll
        for (int i = 0; i < 2; ++i) {
            uint32_t moff = (uint32_t)(wm*32 + i*16)*AROW + a_off;
            uint32_t aa[4], ag[4];
            ldsm4(aa, cur + 0*ABUF + moff);
            ldsm4(ag, cur + 1*ABUF + moff);
            #pragma unroll
            for (int j = 0; j < 4; ++j) {
                mma16816(acc_a[i][j], aa, bh[2*j], bh[2*j+1]);
                mma16816(acc_g[i][j], ag, bh[2*j], bh[2*j+1]);
            }
        }
        if (++cur_s == 3) cur_s = 0;
    }

    #pragma unroll
    for (int i = 0; i < 2; ++i) {
        int hr = h0 + wm*32 + i*16 + (lane >> 2);
        float ba0 = bias[hr],     bg0 = bias[Hh + hr];
        float ba1 = bias[hr + 8], bg1 = bias[Hh + hr + 8];
        #pragma unroll
        for (int j = 0; j < 4; ++j) {
            int col = l0 + wn*32 + j*8 + (lane & 3)*2;
            float a0 = acc_a[i][j][0] + ba0, g0 = acc_g[i][j][0] + bg0;
            float a1 = acc_a[i][j][1] + ba0, g1 = acc_g[i][j][1] + bg0;
            float a2 = acc_a[i][j][2] + ba1, g2 = acc_g[i][j][2] + bg1;
            float a3 = acc_a[i][j][3] + ba1, g3 = acc_g[i][j][3] + bg1;
            float2 v0 = make_float2(a0 / (1.0f + expf(-g0)),
                                    a1 / (1.0f + expf(-g1)));
            float2 v1 = make_float2(a2 / (1.0f + expf(-g2)),
                                    a3 / (1.0f + expf(-g3)));
            *(float2*)(out + ((size_t)b*Hh + hr)*Ll + col)     = v0;
            *(float2*)(out + ((size_t)b*Hh + hr + 8)*Ll + col) = v1;
        }
    }
}

// ============================================================
extern "C" void kernel_launch(void* const* d_in, const int* in_sizes, int n_in,
                              void* d_out, int out_size) {
    const float* u       = (const float*)d_in[0];
    const float* log_dt  = (const float*)d_in[1];
    const float* C       = (const float*)d_in[2];
    const float* lar     = (const float*)d_in[3];
    const float* aim     = (const float*)d_in[4];
    const float* D       = (const float*)d_in[5];
    const float* Wm      = (const float*)d_in[6];
    const float* bias    = (const float*)d_in[7];
    float* out = (float*)d_out;

    cudaFuncSetAttribute(gemm_mma_kernel,
                         cudaFuncAttributeMaxDynamicSharedMemorySize, GEMM_SMEM);
    cudaFuncSetAttribute(gemmY_kernel,
                         cudaFuncAttributeMaxDynamicSharedMemorySize, YSMEM);

    prep_kernel<<<(Hh*N2d + 255)/256, 256>>>(log_dt, C, lar, aim);
    wsplit_kernel<<<(2*Hh*Hh + 255)/256, 256>>>(Wm);
    ucvt_kernel<<<(Bb*Hh*Ll/4)/256, 256>>>(u);
    powers_kernel<<<Hh/8, 256>>>();
    gemmS_kernel<<<dim3(NCOL/128, Hh), 256>>>();
    chain_kernel<<<(Bb*Hh)/8, 256>>>();
    gemmY_kernel<<<dim3(NCOL/128, Hh), 256, YSMEM>>>(u, D);
    dim3 grid(Ll/128, Hh/128, Bb);
    gemm_mma_kernel<<<grid, 512, GEMM_SMEM>>>(bias, out);
}

// round 16
// speedup vs baseline: 1.4511x; 1.2128x over previous
#include <cuda_runtime.h>
#include <cuda_fp16.h>
#include <math.h>
#include <stdint.h>

#define Hh 256
#define N2d 32
#define Bb 8
#define Ll 4096
#define LC 64
#define NC 64          // chunks per (b,h)
#define NCOL 512       // Bb*NC

// -------- scratch (no allocations allowed) --------
__device__ float g_lam_re[Hh*N2d], g_lam_im[Hh*N2d];
__device__ float g_c_re[Hh*N2d],   g_c_im[Hh*N2d];
__device__ float g_lamK_re[Hh*N2d], g_lamK_im[Hh*N2d];          // lambda^64
__device__ __align__(16) __half g_u16[(size_t)Bb*Hh*Ll];        // u in fp16
__device__ __align__(16) __half g_VT[Hh*64*64];                 // VT[h][k=j][n']
__device__ __align__(16) __half g_KET[(size_t)Hh*128*64];       // [K|E]^T[h][k][i]
__device__ float g_ST[(size_t)Hh*NCOL*64];                      // S^T[h][col][n']
__device__ __align__(16) __half g_TinitT[(size_t)Hh*NCOL*64];   // Tinit^T[h][col][n']
__device__ __align__(16) __half g_Wh[2*Hh*Hh];
__device__ __align__(16) __half g_Yh[(size_t)Bb*Hh*Ll];         // post-GELU activations

__device__ __forceinline__ uint32_t smem_u32(const void* p) {
    uint32_t a;
    asm("{ .reg .u64 t; cvta.to.shared.u64 t, %1; cvt.u32.u64 %0, t; }" : "=r"(a) : "l"(p));
    return a;
}
__device__ __forceinline__ void ldsm4(uint32_t* r, uint32_t a) {
    asm volatile("ldmatrix.sync.aligned.m8n8.x4.shared.b16 {%0,%1,%2,%3}, [%4];"
                 : "=r"(r[0]), "=r"(r[1]), "=r"(r[2]), "=r"(r[3]) : "r"(a));
}
__device__ __forceinline__ void ldsm4t(uint32_t* r, uint32_t a) {
    asm volatile("ldmatrix.sync.aligned.m8n8.x4.trans.shared.b16 {%0,%1,%2,%3}, [%4];"
                 : "=r"(r[0]), "=r"(r[1]), "=r"(r[2]), "=r"(r[3]) : "r"(a));
}
__device__ __forceinline__ void mma16816(float* c, const uint32_t* a,
                                         uint32_t b0, uint32_t b1) {
    asm volatile(
        "mma.sync.aligned.m16n8k16.row.col.f32.f16.f16.f32 "
        "{%0,%1,%2,%3}, {%4,%5,%6,%7}, {%8,%9}, {%0,%1,%2,%3};"
        : "+f"(c[0]), "+f"(c[1]), "+f"(c[2]), "+f"(c[3])
        : "r"(a[0]), "r"(a[1]), "r"(a[2]), "r"(a[3]), "r"(b0), "r"(b1));
}
__device__ __forceinline__ void cpa16(uint32_t dst, const void* src) {
    asm volatile("cp.async.cg.shared.global [%0], [%1], 16;" :: "r"(dst), "l"(src));
}
__device__ __forceinline__ void cp_commit_wait0() {
    asm volatile("cp.async.commit_group;" ::: "memory");
    asm volatile("cp.async.wait_group 0;" ::: "memory");
}
__device__ __forceinline__ float gelu_exact(float y) {
    return 0.5f*y*(1.0f + erff(y*0.70710678118654752f));
}

// ============================================================
// 1a: discretization; also lambda^64 by 6 complex squarings.
// ============================================================
__global__ void prep_kernel(const float* __restrict__ log_dt,
                            const float* __restrict__ C,
                            const float* __restrict__ log_A_real,
                            const float* __restrict__ A_imag) {
    int idx = blockIdx.x*blockDim.x + threadIdx.x;
    if (idx >= Hh*N2d) return;
    int h = idx / N2d;
    float dt  = expf(log_dt[h]);
    float Are = -expf(log_A_real[idx]);
    float Aim = A_imag[idx];
    float dr = Are*dt, di = Aim*dt;
    float er = expf(dr);
    float lr = er*cosf(di), li = er*sinf(di);
    float e1r = lr - 1.0f, e1i = li;
    float den = Are*Are + Aim*Aim;
    float ir =  Are/den, ii = -Aim/den;
    float tr = e1r*ir - e1i*ii;
    float ti = e1r*ii + e1i*ir;
    float Cr = C[2*idx], Ci = C[2*idx+1];
    g_lam_re[idx] = lr;  g_lam_im[idx] = li;
    g_c_re[idx] = 2.0f*(Cr*tr - Ci*ti);
    g_c_im[idx] = 2.0f*(Cr*ti + Ci*tr);
    float pr = lr, pi = li;
    #pragma unroll
    for (int s = 0; s < 6; ++s) {      // lambda^(2^6) = lambda^64
        float nr = pr*pr - pi*pi;
        float ni = 2.0f*pr*pi;
        pr = nr; pi = ni;
    }
    g_lamK_re[idx] = pr; g_lamK_im[idx] = pi;
}

// ============================================================
// 1b: W -> fp16
// ============================================================
__global__ void wsplit_kernel(const float* __restrict__ W) {
    int i = blockIdx.x*blockDim.x + threadIdx.x;
    if (i >= 2*Hh*Hh) return;
    g_Wh[i] = __float2half(W[i]);
}

// ============================================================
// 1c: u -> fp16
// ============================================================
__global__ void ucvt_kernel(const float* __restrict__ u) {
    int i = blockIdx.x*blockDim.x + threadIdx.x;     // per float4
    float4 v = ((const float4*)u)[i];
    ((__half2*)g_u16)[i*2]   = __floats2half2_rn(v.x, v.y);
    ((__half2*)g_u16)[i*2+1] = __floats2half2_rn(v.z, v.w);
}

// ============================================================
// 1d: powers — PARALLEL over d. Block = one h (256 blocks),
// warp w handles d = it*8+w, lane = mode n. lambda^d by binary
// exponentiation (uniform per warp). Skip D folded into kk[0].
// ============================================================
__global__ void __launch_bounds__(256) powers_kernel(const float* __restrict__ D) {
    __shared__ float kk[64];
    int h = blockIdx.x;
    int w = threadIdx.x >> 5, lane = threadIdx.x & 31;
    int ci = h*N2d + lane;
    float lr = g_lam_re[ci], li = g_lam_im[ci];
    float cr = g_c_re[ci],   cim = g_c_im[ci];
    float Dh = D[h];
    __half* vt  = g_VT  + (size_t)h*4096;
    __half* ket = g_KET + (size_t)h*8192;
    #pragma unroll
    for (int it = 0; it < 8; ++it) {
        int d = it*8 + w;
        // p = lam^d via 6-bit binary exponentiation
        float pr = 1.0f, pi = 0.0f;
        float br = lr,  bi = li;
        int e = d;
        #pragma unroll
        for (int bit = 0; bit < 6; ++bit) {
            if (e & 1) {
                float nr = pr*br - pi*bi, ni = pr*bi + pi*br;
                pr = nr; pi = ni;
            }
            float sr = br*br - bi*bi, si = 2.0f*br*bi;
            br = sr; bi = si;
            e >>= 1;
        }
        float re = cr*pr - cim*pi;
        float im = cr*pi + cim*pr;
        vt[(63-d)*64 + lane]      = __float2half(re);
        vt[(63-d)*64 + 32 + lane] = __float2half(im);
        float qr = pr*lr - pi*li, qi = pr*li + pi*lr;   // lam^{d+1}
        ket[(64+lane)*64 + d] = __float2half(qr);
        ket[(96+lane)*64 + d] = __float2half(-qi);
        float s = re;
        #pragma unroll
        for (int o = 16; o > 0; o >>= 1) s += __shfl_xor_sync(0xffffffffu, s, o);
        if (lane == 0) kk[d] = s + (d == 0 ? Dh : 0.0f);   // skip folded in
    }
    __syncthreads();
    for (int t = threadIdx.x; t < 4096; t += 256) {
        int k = t >> 6, i = t & 63;
        ket[k*64 + i] = (i >= k) ? __float2half(kk[i-k]) : __float2half(0.0f);
    }
}

// ============================================================
// 2: GEMM-S:  S^T[col][n'] = sum_j u16[col][j] * VT[j][n']
// ============================================================
#define SAROW 144
#define SBROW 144
__global__ void __launch_bounds__(256) gemmS_kernel() {
    __shared__ char smem[128*SAROW + 64*SBROW];
    uint32_t sb  = smem_u32(smem);
    uint32_t sbB = sb + 128*SAROW;
    int tid = threadIdx.x, lane = tid & 31, w = tid >> 5;
    int wm = w >> 1, wn = w & 1;
    int h = blockIdx.y;
    int gm0 = blockIdx.x*128;
    #pragma unroll
    for (int t = 0; t < 4; ++t) {
        int id = tid + t*256;
        int row = id >> 3, seg = id & 7;
        int gm = gm0 + row, b = gm >> 6, cc = gm & 63;
        cpa16(sb + row*SAROW + seg*16,
              g_u16 + ((size_t)(b*Hh + h)*Ll + cc*64) + seg*8);
    }
    #pragma unroll
    for (int t = 0; t < 2; ++t) {
        int id = tid + t*256;
        int row = id >> 3, seg = id & 7;
        cpa16(sbB + row*SBROW + seg*16, g_VT + (size_t)h*4096 + row*64 + seg*8);
    }
    cp_commit_wait0();
    __syncthreads();
    const uint32_t a_off = (lane & 15)*SAROW + (lane >> 4)*16;
    const uint32_t b_off = ((lane & 7) + ((lane >> 3) & 1)*8)*SBROW + (lane >> 4)*16;
    float acc[2][4][4];
    #pragma unroll
    for (int i = 0; i < 2; ++i)
        #pragma unroll
        for (int j = 0; j < 4; ++j)
            #pragma unroll
            for (int q = 0; q < 4; ++q) acc[i][j][q] = 0.f;
    #pragma unroll
    for (int ks = 0; ks < 4; ++ks) {
        uint32_t bh[8];
        uint32_t bas = sbB + (uint32_t)(ks*16)*SBROW + b_off + (uint32_t)(wn*64);
        ldsm4t(&bh[0], bas);
        ldsm4t(&bh[4], bas + 32);
        #pragma unroll
        for (int i = 0; i < 2; ++i) {
            uint32_t aa[4];
            ldsm4(aa, sb + (uint32_t)(wm*32 + i*16)*SAROW + (uint32_t)(ks*32) + a_off);
            #pragma unroll
            for (int j = 0; j < 4; ++j)
                mma16816(acc[i][j], aa, bh[2*j], bh[2*j+1]);
        }
    }
    float* stp = g_ST + ((size_t)h*NCOL + gm0)*64;
    #pragma unroll
    for (int i = 0; i < 2; ++i) {
        int rm = wm*32 + i*16 + (lane >> 2);
        #pragma unroll
        for (int j = 0; j < 4; ++j) {
            int cn = wn*32 + j*8 + (lane & 3)*2;
            *(float2*)(stp + (size_t)rm*64 + cn)     = make_float2(acc[i][j][0], acc[i][j][1]);
            *(float2*)(stp + (size_t)(rm+8)*64 + cn) = make_float2(acc[i][j][2], acc[i][j][3]);
        }
    }
}

// ============================================================
// 3: chain — serial state propagation across 64 chunks.
// ============================================================
__global__ void __launch_bounds__(256) chain_kernel() {
    int w = threadIdx.x >> 5, lane = threadIdx.x & 31;
    int wid = blockIdx.x*8 + w;           // 0..2047
    int b = wid >> 8, h = wid & 255;
    int ci = h*N2d + lane;
    float kr = g_lamK_re[ci], ki = g_lamK_im[ci];
    float tr = 0.f, ti = 0.f;
    const float* st = g_ST     + ((size_t)h*NCOL + b*64)*64;
    __half*      tt = g_TinitT + ((size_t)h*NCOL + b*64)*64;
    #pragma unroll 1
    for (int c = 0; c < 64; ++c) {
        tt[(size_t)c*64 + lane]      = __float2half(tr);
        tt[(size_t)c*64 + 32 + lane] = __float2half(ti);
        float sre = st[(size_t)c*64 + lane];
        float sim = st[(size_t)c*64 + 32 + lane];
        float nr = fmaf(kr, tr, fmaf(-ki, ti, sre));
        float ni = fmaf(kr, ti, fmaf( ki, tr, sim));
        tr = nr; ti = ni;
    }
}

// ============================================================
// 4: GEMM-Y:  y^T[col][i] = sum_k [u16|Tinit][col][k] * KET[k][i]
// (skip already folded into KET diag) + exact GELU -> g_Yh.
// ============================================================
#define YAROW 272
#define YBROW 144
#define YSMEM (128*YAROW + 128*YBROW)   // 53248
__global__ void __launch_bounds__(256) gemmY_kernel() {
    extern __shared__ char ysmem[];
    uint32_t sb  = smem_u32(ysmem);
    uint32_t sbB = sb + 128*YAROW;
    int tid = threadIdx.x, lane = tid & 31, w = tid >> 5;
    int wm = w >> 1, wn = w & 1;
    int h = blockIdx.y;
    int gm0 = blockIdx.x*128;
    #pragma unroll
    for (int t = 0; t < 8; ++t) {
        int id = tid + t*256;
        int row = id >> 4, seg = id & 15;
        int gm = gm0 + row, b = gm >> 6, cc = gm & 63;
        const __half* src = (seg < 8)
            ? g_u16 + ((size_t)(b*Hh + h)*Ll + cc*64) + seg*8
            : g_TinitT + ((size_t)h*NCOL + gm)*64 + (seg-8)*8;
        cpa16(sb + row*YAROW + seg*16, src);
    }
    #pragma unroll
    for (int t = 0; t < 4; ++t) {
        int id = tid + t*256;
        int row = id >> 3, seg = id & 7;
        cpa16(sbB + row*YBROW + seg*16, g_KET + (size_t)h*8192 + row*64 + seg*8);
    }
    cp_commit_wait0();
    __syncthreads();
    const uint32_t a_off = (lane & 15)*YAROW + (lane >> 4)*16;
    const uint32_t b_off = ((lane & 7) + ((lane >> 3) & 1)*8)*YBROW + (lane >> 4)*16;
    float acc[2][4][4];
    #pragma unroll
    for (int i = 0; i < 2; ++i)
        #pragma unroll
        for (int j = 0; j < 4; ++j)
            #pragma unroll
            for (int q = 0; q < 4; ++q) acc[i][j][q] = 0.f;
    #pragma unroll
    for (int ks = 0; ks < 8; ++ks) {
        uint32_t bh[8];
        uint32_t bas = sbB + (uint32_t)(ks*16)*YBROW + b_off + (uint32_t)(wn*64);
        ldsm4t(&bh[0], bas);
        ldsm4t(&bh[4], bas + 32);
        #pragma unroll
        for (int i = 0; i < 2; ++i) {
            uint32_t aa[4];
            ldsm4(aa, sb + (uint32_t)(wm*32 + i*16)*YAROW + (uint32_t)(ks*32) + a_off);
            #pragma unroll
            for (int j = 0; j < 4; ++j)
                mma16816(acc[i][j], aa, bh[2*j], bh[2*j+1]);
        }
    }
    #pragma unroll
    for (int i = 0; i < 2; ++i) {
        #pragma unroll
        for (int qq = 0; qq < 2; ++qq) {
            int rm = wm*32 + i*16 + (lane >> 2) + qq*8;
            int gm = gm0 + rm, b = gm >> 6, cc = gm & 63;
            size_t rowbase = (size_t)(b*Hh + h)*Ll + cc*64;
            #pragma unroll
            for (int j = 0; j < 4; ++j) {
                int cn = wn*32 + j*8 + (lane & 3)*2;
                *(__half2*)(g_Yh + rowbase + cn) =
                    __floats2half2_rn(gelu_exact(acc[i][j][qq*2 + 0]),
                                      gelu_exact(acc[i][j][qq*2 + 1]));
            }
        }
    }
}

// ============================================================
// 5: HMMA fp16 W-GEMM + bias + GLU (R12, ~50us, unchanged).
// ============================================================
#define AROW 48
#define ABUF (128*AROW)
#define BROW 272
#define BBUF (16*BROW)
#define BOFF (2*ABUF)
#define STAGEB (2*ABUF + BBUF)
#define GEMM_SMEM (3*STAGEB)

__global__ void __launch_bounds__(512, 1) gemm_mma_kernel(const float* __restrict__ bias,
                                                          float* __restrict__ out) {
    extern __shared__ char smem[];
    const uint32_t sb = smem_u32(smem);
    const int tid  = threadIdx.x;
    const int lane = tid & 31;
    const int w    = tid >> 5;
    const int wm   = w >> 2;
    const int wn   = w & 3;
    const int l0 = blockIdx.x*128;
    const int h0 = blockIdx.y*128;
    const int b  = blockIdx.z;

    const int aarr = tid >> 8;
    const int arow = (tid & 255) >> 1, aseg = tid & 1;
    const __half* pA = g_Wh + (size_t)(aarr*Hh + h0 + arow)*Hh + aseg*8;
    const uint32_t aDst = (uint32_t)(aarr*ABUF + arow*AROW + aseg*16);
    const int brow = (tid >> 4) & 15, bch = tid & 15;
    const __half* pB = g_Yh + ((size_t)b*Hh + brow)*Ll + l0 + bch*8;
    const uint32_t bDst = (uint32_t)(BOFF + brow*BROW + bch*16);
    const bool doB = (tid < 256);

    const uint32_t a_off = (uint32_t)((lane & 15)*AROW + (lane >> 4)*16);
    const uint32_t b_off = (uint32_t)(((lane & 7) + ((lane >> 3) & 1)*8)*BROW
                                      + (lane >> 4)*16);

    float acc_a[2][4][4], acc_g[2][4][4];
    #pragma unroll
    for (int i = 0; i < 2; ++i)
        #pragma unroll
        for (int j = 0; j < 4; ++j)
            #pragma unroll
            for (int q = 0; q < 4; ++q) { acc_a[i][j][q] = 0.f; acc_g[i][j][q] = 0.f; }

    #pragma unroll
    for (int s = 0; s < 2; ++s) {
        uint32_t st = sb + (uint32_t)s*STAGEB;
        cpa16(st + aDst, pA + s*16);
        if (doB) cpa16(st + bDst, pB + (size_t)s*16*Ll);
        asm volatile("cp.async.commit_group;" ::: "memory");
    }

    int cur_s = 0;
    #pragma unroll 1
    for (int ks = 0; ks < 16; ++ks) {
        if (ks < 15) asm volatile("cp.async.wait_group 1;" ::: "memory");
        else         asm volatile("cp.async.wait_group 0;" ::: "memory");
        __syncthreads();
        if (ks + 2 < 16) {
            int s = ks + 2;
            int ss = cur_s + 2; if (ss >= 3) ss -= 3;
            uint32_t st = sb + (uint32_t)ss*STAGEB;
            cpa16(st + aDst, pA + s*16);
            if (doB) cpa16(st + bDst, pB + (size_t)s*16*Ll);
            asm volatile("cp.async.commit_group;" ::: "memory");
        }
        const uint32_t cur = sb + (uint32_t)cur_s*STAGEB;
        uint32_t bh[8];
        {
            uint32_t bas = cur + BOFF + b_off + (uint32_t)(wn*64);
            ldsm4t(&bh[0], bas);
            ldsm4t(&bh[4], bas + 32);
        }
        #pragma unroll
        for (int i = 0; i < 2; ++i) {
            uint32_t moff = (uint32_t)(wm*32 + i*16)*AROW + a_off;
            uint32_t aa[4], ag[4];
            ldsm4(aa, cur + 0*ABUF + moff);
            ldsm4(ag, cur + 1*ABUF + moff);
            #pragma unroll
            for (int j = 0; j < 4; ++j) {
                mma16816(acc_a[i][j], aa, bh[2*j], bh[2*j+1]);
                mma16816(acc_g[i][j], ag, bh[2*j], bh[2*j+1]);
            }
        }
        if (++cur_s == 3) cur_s = 0;
    }

    #pragma unroll
    for (int i = 0; i < 2; ++i) {
        int hr = h0 + wm*32 + i*16 + (lane >> 2);
        float ba0 = bias[hr],     bg0 = bias[Hh + hr];
        float ba1 = bias[hr + 8], bg1 = bias[Hh + hr + 8];
        #pragma unroll
        for (int j = 0; j < 4; ++j) {
            int col = l0 + wn*32 + j*8 + (lane & 3)*2;
            float a0 = acc_a[i][j][0] + ba0, g0 = acc_g[i][j][0] + bg0;
            float a1 = acc_a[i][j][1] + ba0, g1 = acc_g[i][j][1] + bg0;
            float a2 = acc_a[i][j][2] + ba1, g2 = acc_g[i][j][2] + bg1;
            float a3 = acc_a[i][j][3] + ba1, g3 = acc_g[i][j][3] + bg1;
            float2 v0 = make_float2(a0 / (1.0f + expf(-g0)),
                                    a1 / (1.0f + expf(-g1)));
            float2 v1 = make_float2(a2 / (1.0f + expf(-g2)),
                                    a3 / (1.0f + expf(-g3)));
            *(float2*)(out + ((size_t)b*Hh + hr)*Ll + col)     = v0;
            *(float2*)(out + ((size_t)b*Hh + hr + 8)*Ll + col) = v1;
        }
    }
}

// ============================================================
extern "C" void kernel_launch(void* const* d_in, const int* in_sizes, int n_in,
                              void* d_out, int out_size) {
    const float* u       = (const float*)d_in[0];
    const float* log_dt  = (const float*)d_in[1];
    const float* C       = (const float*)d_in[2];
    const float* lar     = (const float*)d_in[3];
    const float* aim     = (const float*)d_in[4];
    const float* D       = (const float*)d_in[5];
    const float* Wm      = (const float*)d_in[6];
    const float* bias    = (const float*)d_in[7];
    float* out = (float*)d_out;

    cudaFuncSetAttribute(gemm_mma_kernel,
                         cudaFuncAttributeMaxDynamicSharedMemorySize, GEMM_SMEM);
    cudaFuncSetAttribute(gemmY_kernel,
                         cudaFuncAttributeMaxDynamicSharedMemorySize, YSMEM);

    prep_kernel<<<(Hh*N2d + 255)/256, 256>>>(log_dt, C, lar, aim);
    wsplit_kernel<<<(2*Hh*Hh + 255)/256, 256>>>(Wm);
    ucvt_kernel<<<(Bb*Hh*Ll/4)/256, 256>>>(u);
    powers_kernel<<<Hh, 256>>>(D);
    gemmS_kernel<<<dim3(NCOL/128, Hh), 256>>>();
    chain_kernel<<<(Bb*Hh)/8, 256>>>();
    gemmY_kernel<<<dim3(NCOL/128, Hh), 256, YSMEM>>>();
    dim3 grid(Ll/128, Hh/128, Bb);
    gemm_mma_kernel<<<grid, 512, GEMM_SMEM>>>(bias, out);
}

// round 17
// speedup vs baseline: 1.5022x; 1.0352x over previous
#include <cuda_runtime.h>
#include <cuda_fp16.h>
#include <math.h>
#include <stdint.h>

#define Hh 256
#define N2d 32
#define Bb 8
#define Ll 4096
#define LC 64
#define NC 64          // chunks per (b,h)
#define NCOL 512       // Bb*NC

// -------- scratch (no allocations allowed) --------
__device__ float g_lam_re[Hh*N2d], g_lam_im[Hh*N2d];
__device__ float g_c_re[Hh*N2d],   g_c_im[Hh*N2d];
__device__ float g_lamK_re[Hh*N2d], g_lamK_im[Hh*N2d];          // lambda^64
__device__ __align__(16) __half g_u16[(size_t)Bb*Hh*Ll];        // u in fp16 (written by gemmS)
__device__ __align__(16) __half g_VT[Hh*64*64];                 // VT[h][k=j][n']
__device__ __align__(16) __half g_KET[(size_t)Hh*128*64];       // [K|E]^T[h][k][i]
__device__ float g_ST[(size_t)Hh*NCOL*64];                      // S^T[h][col][n']
__device__ __align__(16) __half g_TinitT[(size_t)Hh*NCOL*64];   // Tinit^T[h][col][n']
__device__ __align__(16) __half g_Wh[2*Hh*Hh];
__device__ __align__(16) __half g_Yh[(size_t)Bb*Hh*Ll];         // post-GELU activations

__device__ __forceinline__ uint32_t smem_u32(const void* p) {
    uint32_t a;
    asm("{ .reg .u64 t; cvta.to.shared.u64 t, %1; cvt.u32.u64 %0, t; }" : "=r"(a) : "l"(p));
    return a;
}
__device__ __forceinline__ void ldsm4(uint32_t* r, uint32_t a) {
    asm volatile("ldmatrix.sync.aligned.m8n8.x4.shared.b16 {%0,%1,%2,%3}, [%4];"
                 : "=r"(r[0]), "=r"(r[1]), "=r"(r[2]), "=r"(r[3]) : "r"(a));
}
__device__ __forceinline__ void ldsm4t(uint32_t* r, uint32_t a) {
    asm volatile("ldmatrix.sync.aligned.m8n8.x4.trans.shared.b16 {%0,%1,%2,%3}, [%4];"
                 : "=r"(r[0]), "=r"(r[1]), "=r"(r[2]), "=r"(r[3]) : "r"(a));
}
__device__ __forceinline__ void mma16816(float* c, const uint32_t* a,
                                         uint32_t b0, uint32_t b1) {
    asm volatile(
        "mma.sync.aligned.m16n8k16.row.col.f32.f16.f16.f32 "
        "{%0,%1,%2,%3}, {%4,%5,%6,%7}, {%8,%9}, {%0,%1,%2,%3};"
        : "+f"(c[0]), "+f"(c[1]), "+f"(c[2]), "+f"(c[3])
        : "r"(a[0]), "r"(a[1]), "r"(a[2]), "r"(a[3]), "r"(b0), "r"(b1));
}
__device__ __forceinline__ void cpa16(uint32_t dst, const void* src) {
    asm volatile("cp.async.cg.shared.global [%0], [%1], 16;" :: "r"(dst), "l"(src));
}
__device__ __forceinline__ void cp_commit_wait0() {
    asm volatile("cp.async.commit_group;" ::: "memory");
    asm volatile("cp.async.wait_group 0;" ::: "memory");
}
__device__ __forceinline__ float gelu_exact(float y) {
    return 0.5f*y*(1.0f + erff(y*0.70710678118654752f));
}

// ============================================================
// 1a: discretization; also lambda^64 by 6 complex squarings.
// ============================================================
__global__ void prep_kernel(const float* __restrict__ log_dt,
                            const float* __restrict__ C,
                            const float* __restrict__ log_A_real,
                            const float* __restrict__ A_imag) {
    int idx = blockIdx.x*blockDim.x + threadIdx.x;
    if (idx >= Hh*N2d) return;
    int h = idx / N2d;
    float dt  = expf(log_dt[h]);
    float Are = -expf(log_A_real[idx]);
    float Aim = A_imag[idx];
    float dr = Are*dt, di = Aim*dt;
    float er = expf(dr);
    float lr = er*cosf(di), li = er*sinf(di);
    float e1r = lr - 1.0f, e1i = li;
    float den = Are*Are + Aim*Aim;
    float ir =  Are/den, ii = -Aim/den;
    float tr = e1r*ir - e1i*ii;
    float ti = e1r*ii + e1i*ir;
    float Cr = C[2*idx], Ci = C[2*idx+1];
    g_lam_re[idx] = lr;  g_lam_im[idx] = li;
    g_c_re[idx] = 2.0f*(Cr*tr - Ci*ti);
    g_c_im[idx] = 2.0f*(Cr*ti + Ci*tr);
    float pr = lr, pi = li;
    #pragma unroll
    for (int s = 0; s < 6; ++s) {
        float nr = pr*pr - pi*pi;
        float ni = 2.0f*pr*pi;
        pr = nr; pi = ni;
    }
    g_lamK_re[idx] = pr; g_lamK_im[idx] = pi;
}

// ============================================================
// 1b: W -> fp16
// ============================================================
__global__ void wsplit_kernel(const float* __restrict__ W) {
    int i = blockIdx.x*blockDim.x + threadIdx.x;
    if (i >= 2*Hh*Hh) return;
    g_Wh[i] = __float2half(W[i]);
}

// ============================================================
// 1d: powers — parallel over d; smem staging + uint4 writeout.
// Block = one h, warp w handles d = it*8+w, lane = mode n.
// Skip D folded into kk[0].
// ============================================================
__global__ void __launch_bounds__(256) powers_kernel(const float* __restrict__ D) {
    __shared__ float kk[64];
    __shared__ __align__(16) __half svt[64*64];
    __shared__ __align__(16) __half sket[128*64];
    int h = blockIdx.x;
    int w = threadIdx.x >> 5, lane = threadIdx.x & 31;
    int ci = h*N2d + lane;
    float lr = g_lam_re[ci], li = g_lam_im[ci];
    float cr = g_c_re[ci],   cim = g_c_im[ci];
    float Dh = D[h];
    #pragma unroll
    for (int it = 0; it < 8; ++it) {
        int d = it*8 + w;
        float pr = 1.0f, pi = 0.0f;
        float br = lr,  bi = li;
        int e = d;
        #pragma unroll
        for (int bit = 0; bit < 6; ++bit) {
            if (e & 1) {
                float nr = pr*br - pi*bi, ni = pr*bi + pi*br;
                pr = nr; pi = ni;
            }
            float sr = br*br - bi*bi, si = 2.0f*br*bi;
            br = sr; bi = si;
            e >>= 1;
        }
        float re = cr*pr - cim*pi;
        float im = cr*pi + cim*pr;
        svt[(63-d)*64 + lane]      = __float2half(re);
        svt[(63-d)*64 + 32 + lane] = __float2half(im);
        float qr = pr*lr - pi*li, qi = pr*li + pi*lr;   // lam^{d+1}
        sket[(64+lane)*64 + d] = __float2half(qr);
        sket[(96+lane)*64 + d] = __float2half(-qi);
        float s = re;
        #pragma unroll
        for (int o = 16; o > 0; o >>= 1) s += __shfl_xor_sync(0xffffffffu, s, o);
        if (lane == 0) kk[d] = s + (d == 0 ? Dh : 0.0f);   // skip folded in
    }
    __syncthreads();
    for (int t = threadIdx.x; t < 4096; t += 256) {
        int k = t >> 6, i = t & 63;
        sket[k*64 + i] = (i >= k) ? __float2half(kk[i-k]) : __float2half(0.0f);
    }
    __syncthreads();
    // vectorized writeout
    uint4* vdst = (uint4*)(g_VT + (size_t)h*4096);
    const uint4* vsrc = (const uint4*)svt;
    #pragma unroll
    for (int t = 0; t < 2; ++t)
        vdst[threadIdx.x + t*256] = vsrc[threadIdx.x + t*256];
    uint4* kdst = (uint4*)(g_KET + (size_t)h*8192);
    const uint4* ksrc = (const uint4*)sket;
    #pragma unroll
    for (int t = 0; t < 4; ++t)
        kdst[threadIdx.x + t*256] = ksrc[threadIdx.x + t*256];
}

// ============================================================
// 2: GEMM-S:  S^T[col][n'] = sum_j u[col][j] * VT[j][n']
// Fused u fp32->fp16: LDG float4 + cvt + STS (A tile) + STG g_u16.
// ============================================================
#define SAROW 144
#define SBROW 144
__global__ void __launch_bounds__(256) gemmS_kernel(const float* __restrict__ uf) {
    __shared__ char smem[128*SAROW + 64*SBROW];
    uint32_t sb  = smem_u32(smem);
    uint32_t sbB = sb + 128*SAROW;
    int tid = threadIdx.x, lane = tid & 31, w = tid >> 5;
    int wm = w >> 1, wn = w & 1;
    int h = blockIdx.y;
    int gm0 = blockIdx.x*128;
    // B: VT 64 rows x 128B via cp.async
    #pragma unroll
    for (int t = 0; t < 2; ++t) {
        int id = tid + t*256;
        int row = id >> 3, seg = id & 7;
        cpa16(sbB + row*SBROW + seg*16, g_VT + (size_t)h*4096 + row*64 + seg*8);
    }
    asm volatile("cp.async.commit_group;" ::: "memory");
    // A: u fp32 -> fp16; 128 rows x 64 floats; also write g_u16.
    #pragma unroll
    for (int t = 0; t < 8; ++t) {
        int id = tid + t*256;
        int row = id >> 4, seg = id & 15;            // 16 x float4 per row
        int gm = gm0 + row, b = gm >> 6, cc = gm & 63;
        size_t base = (size_t)(b*Hh + h)*Ll + cc*64 + seg*4;
        float4 v = *(const float4*)(uf + base);
        __half2 p0 = __floats2half2_rn(v.x, v.y);
        __half2 p1 = __floats2half2_rn(v.z, v.w);
        uint2 pk = make_uint2(*(uint32_t*)&p0, *(uint32_t*)&p1);
        *(uint2*)(smem + row*SAROW + seg*8) = pk;
        *(uint2*)(g_u16 + base) = pk;
    }
    asm volatile("cp.async.wait_group 0;" ::: "memory");
    __syncthreads();
    const uint32_t a_off = (lane & 15)*SAROW + (lane >> 4)*16;
    const uint32_t b_off = ((lane & 7) + ((lane >> 3) & 1)*8)*SBROW + (lane >> 4)*16;
    float acc[2][4][4];
    #pragma unroll
    for (int i = 0; i < 2; ++i)
        #pragma unroll
        for (int j = 0; j < 4; ++j)
            #pragma unroll
            for (int q = 0; q < 4; ++q) acc[i][j][q] = 0.f;
    #pragma unroll
    for (int ks = 0; ks < 4; ++ks) {
        uint32_t bh[8];
        uint32_t bas = sbB + (uint32_t)(ks*16)*SBROW + b_off + (uint32_t)(wn*64);
        ldsm4t(&bh[0], bas);
        ldsm4t(&bh[4], bas + 32);
        #pragma unroll
        for (int i = 0; i < 2; ++i) {
            uint32_t aa[4];
            ldsm4(aa, sb + (uint32_t)(wm*32 + i*16)*SAROW + (uint32_t)(ks*32) + a_off);
            #pragma unroll
            for (int j = 0; j < 4; ++j)
                mma16816(acc[i][j], aa, bh[2*j], bh[2*j+1]);
        }
    }
    float* stp = g_ST + ((size_t)h*NCOL + gm0)*64;
    #pragma unroll
    for (int i = 0; i < 2; ++i) {
        int rm = wm*32 + i*16 + (lane >> 2);
        #pragma unroll
        for (int j = 0; j < 4; ++j) {
            int cn = wn*32 + j*8 + (lane & 3)*2;
            *(float2*)(stp + (size_t)rm*64 + cn)     = make_float2(acc[i][j][0], acc[i][j][1]);
            *(float2*)(stp + (size_t)(rm+8)*64 + cn) = make_float2(acc[i][j][2], acc[i][j][3]);
        }
    }
}

// ============================================================
// 3: chain — serial state propagation, next-S prefetch.
// ============================================================
__global__ void __launch_bounds__(256) chain_kernel() {
    int w = threadIdx.x >> 5, lane = threadIdx.x & 31;
    int wid = blockIdx.x*8 + w;           // 0..2047
    int b = wid >> 8, h = wid & 255;
    int ci = h*N2d + lane;
    float kr = g_lamK_re[ci], ki = g_lamK_im[ci];
    float tr = 0.f, ti = 0.f;
    const float* st = g_ST     + ((size_t)h*NCOL + b*64)*64;
    __half*      tt = g_TinitT + ((size_t)h*NCOL + b*64)*64;
    float sre = st[lane], sim = st[32 + lane];
    #pragma unroll 1
    for (int c = 0; c < 64; ++c) {
        float nsre = 0.f, nsim = 0.f;
        if (c < 63) {
            nsre = st[(size_t)(c+1)*64 + lane];
            nsim = st[(size_t)(c+1)*64 + 32 + lane];
        }
        tt[(size_t)c*64 + lane]      = __float2half(tr);
        tt[(size_t)c*64 + 32 + lane] = __float2half(ti);
        float nr = fmaf(kr, tr, fmaf(-ki, ti, sre));
        float ni = fmaf(kr, ti, fmaf( ki, tr, sim));
        tr = nr; ti = ni;
        sre = nsre; sim = nsim;
    }
}

// ============================================================
// 4: GEMM-Y:  y^T[col][i] = sum_k [u16|Tinit][col][k] * KET[k][i]
// (skip folded into KET diag) + exact GELU -> g_Yh.
// ============================================================
#define YAROW 272
#define YBROW 144
#define YSMEM (128*YAROW + 128*YBROW)   // 53248
__global__ void __launch_bounds__(256) gemmY_kernel() {
    extern __shared__ char ysmem[];
    uint32_t sb  = smem_u32(ysmem);
    uint32_t sbB = sb + 128*YAROW;
    int tid = threadIdx.x, lane = tid & 31, w = tid >> 5;
    int wm = w >> 1, wn = w & 1;
    int h = blockIdx.y;
    int gm0 = blockIdx.x*128;
    #pragma unroll
    for (int t = 0; t < 8; ++t) {
        int id = tid + t*256;
        int row = id >> 4, seg = id & 15;
        int gm = gm0 + row, b = gm >> 6, cc = gm & 63;
        const __half* src = (seg < 8)
            ? g_u16 + ((size_t)(b*Hh + h)*Ll + cc*64) + seg*8
            : g_TinitT + ((size_t)h*NCOL + gm)*64 + (seg-8)*8;
        cpa16(sb + row*YAROW + seg*16, src);
    }
    #pragma unroll
    for (int t = 0; t < 4; ++t) {
        int id = tid + t*256;
        int row = id >> 3, seg = id & 7;
        cpa16(sbB + row*YBROW + seg*16, g_KET + (size_t)h*8192 + row*64 + seg*8);
    }
    cp_commit_wait0();
    __syncthreads();
    const uint32_t a_off = (lane & 15)*YAROW + (lane >> 4)*16;
    const uint32_t b_off = ((lane & 7) + ((lane >> 3) & 1)*8)*YBROW + (lane >> 4)*16;
    float acc[2][4][4];
    #pragma unroll
    for (int i = 0; i < 2; ++i)
        #pragma unroll
        for (int j = 0; j < 4; ++j)
            #pragma unroll
            for (int q = 0; q < 4; ++q) acc[i][j][q] = 0.f;
    #pragma unroll
    for (int ks = 0; ks < 8; ++ks) {
        uint32_t bh[8];
        uint32_t bas = sbB + (uint32_t)(ks*16)*YBROW + b_off + (uint32_t)(wn*64);
        ldsm4t(&bh[0], bas);
        ldsm4t(&bh[4], bas + 32);
        #pragma unroll
        for (int i = 0; i < 2; ++i) {
            uint32_t aa[4];
            ldsm4(aa, sb + (uint32_t)(wm*32 + i*16)*YAROW + (uint32_t)(ks*32) + a_off);
            #pragma unroll
            for (int j = 0; j < 4; ++j)
                mma16816(acc[i][j], aa, bh[2*j], bh[2*j+1]);
        }
    }
    #pragma unroll
    for (int i = 0; i < 2; ++i) {
        #pragma unroll
        for (int qq = 0; qq < 2; ++qq) {
            int rm = wm*32 + i*16 + (lane >> 2) + qq*8;
            int gm = gm0 + rm, b = gm >> 6, cc = gm & 63;
            size_t rowbase = (size_t)(b*Hh + h)*Ll + cc*64;
            #pragma unroll
            for (int j = 0; j < 4; ++j) {
                int cn = wn*32 + j*8 + (lane & 3)*2;
                *(__half2*)(g_Yh + rowbase + cn) =
                    __floats2half2_rn(gelu_exact(acc[i][j][qq*2 + 0]),
                                      gelu_exact(acc[i][j][qq*2 + 1]));
            }
        }
    }
}

// ============================================================
// 5: HMMA fp16 W-GEMM + bias + GLU (R12, ~50us, unchanged).
// ============================================================
#define AROW 48
#define ABUF (128*AROW)
#define BROW 272
#define BBUF (16*BROW)
#define BOFF (2*ABUF)
#define STAGEB (2*ABUF + BBUF)
#define GEMM_SMEM (3*STAGEB)

__global__ void __launch_bounds__(512, 1) gemm_mma_kernel(const float* __restrict__ bias,
                                                          float* __restrict__ out) {
    extern __shared__ char smem[];
    const uint32_t sb = smem_u32(smem);
    const int tid  = threadIdx.x;
    const int lane = tid & 31;
    const int w    = tid >> 5;
    const int wm   = w >> 2;
    const int wn   = w & 3;
    const int l0 = blockIdx.x*128;
    const int h0 = blockIdx.y*128;
    const int b  = blockIdx.z;

    const int aarr = tid >> 8;
    const int arow = (tid & 255) >> 1, aseg = tid & 1;
    const __half* pA = g_Wh + (size_t)(aarr*Hh + h0 + arow)*Hh + aseg*8;
    const uint32_t aDst = (uint32_t)(aarr*ABUF + arow*AROW + aseg*16);
    const int brow = (tid >> 4) & 15, bch = tid & 15;
    const __half* pB = g_Yh + ((size_t)b*Hh + brow)*Ll + l0 + bch*8;
    const uint32_t bDst = (uint32_t)(BOFF + brow*BROW + bch*16);
    const bool doB = (tid < 256);

    const uint32_t a_off = (uint32_t)((lane & 15)*AROW + (lane >> 4)*16);
    const uint32_t b_off = (uint32_t)(((lane & 7) + ((lane >> 3) & 1)*8)*BROW
                                      + (lane >> 4)*16);

    float acc_a[2][4][4], acc_g[2][4][4];
    #pragma unroll
    for (int i = 0; i < 2; ++i)
        #pragma unroll
        for (int j = 0; j < 4; ++j)
            #pragma unroll
            for (int q = 0; q < 4; ++q) { acc_a[i][j][q] = 0.f; acc_g[i][j][q] = 0.f; }

    #pragma unroll
    for (int s = 0; s < 2; ++s) {
        uint32_t st = sb + (uint32_t)s*STAGEB;
        cpa16(st + aDst, pA + s*16);
        if (doB) cpa16(st + bDst, pB + (size_t)s*16*Ll);
        asm volatile("cp.async.commit_group;" ::: "memory");
    }

    int cur_s = 0;
    #pragma unroll 1
    for (int ks = 0; ks < 16; ++ks) {
        if (ks < 15) asm volatile("cp.async.wait_group 1;" ::: "memory");
        else         asm volatile("cp.async.wait_group 0;" ::: "memory");
        __syncthreads();
        if (ks + 2 < 16) {
            int s = ks + 2;
            int ss = cur_s + 2; if (ss >= 3) ss -= 3;
            uint32_t st = sb + (uint32_t)ss*STAGEB;
            cpa16(st + aDst, pA + s*16);
            if (doB) cpa16(st + bDst, pB + (size_t)s*16*Ll);
            asm volatile("cp.async.commit_group;" ::: "memory");
        }
        const uint32_t cur = sb + (uint32_t)cur_s*STAGEB;
        uint32_t bh[8];
        {
            uint32_t bas = cur + BOFF + b_off + (uint32_t)(wn*64);
            ldsm4t(&bh[0], bas);
            ldsm4t(&bh[4], bas + 32);
        }
        #pragma unroll
        for (int i = 0; i < 2; ++i) {
            uint32_t moff = (uint32_t)(wm*32 + i*16)*AROW + a_off;
            uint32_t aa[4], ag[4];
            ldsm4(aa, cur + 0*ABUF + moff);
            ldsm4(ag, cur + 1*ABUF + moff);
            #pragma unroll
            for (int j = 0; j < 4; ++j) {
                mma16816(acc_a[i][j], aa, bh[2*j], bh[2*j+1]);
                mma16816(acc_g[i][j], ag, bh[2*j], bh[2*j+1]);
            }
        }
        if (++cur_s == 3) cur_s = 0;
    }

    #pragma unroll
    for (int i = 0; i < 2; ++i) {
        int hr = h0 + wm*32 + i*16 + (lane >> 2);
        float ba0 = bias[hr],     bg0 = bias[Hh + hr];
        float ba1 = bias[hr + 8], bg1 = bias[Hh + hr + 8];
        #pragma unroll
        for (int j = 0; j < 4; ++j) {
            int col = l0 + wn*32 + j*8 + (lane & 3)*2;
            float a0 = acc_a[i][j][0] + ba0, g0 = acc_g[i][j][0] + bg0;
            float a1 = acc_a[i][j][1] + ba0, g1 = acc_g[i][j][1] + bg0;
            float a2 = acc_a[i][j][2] + ba1, g2 = acc_g[i][j][2] + bg1;
            float a3 = acc_a[i][j][3] + ba1, g3 = acc_g[i][j][3] + bg1;
            float2 v0 = make_float2(a0 / (1.0f + expf(-g0)),
                                    a1 / (1.0f + expf(-g1)));
            float2 v1 = make_float2(a2 / (1.0f + expf(-g2)),
                                    a3 / (1.0f + expf(-g3)));
            *(float2*)(out + ((size_t)b*Hh + hr)*Ll + col)     = v0;
            *(float2*)(out + ((size_t)b*Hh + hr + 8)*Ll + col) = v1;
        }
    }
}

// ============================================================
extern "C" void kernel_launch(void* const* d_in, const int* in_sizes, int n_in,
                              void* d_out, int out_size) {
    const float* u       = (const float*)d_in[0];
    const float* log_dt  = (const float*)d_in[1];
    const float* C       = (const float*)d_in[2];
    const float* lar     = (const float*)d_in[3];
    const float* aim     = (const float*)d_in[4];
    const float* D       = (const float*)d_in[5];
    const float* Wm      = (const float*)d_in[6];
    const float* bias    = (const float*)d_in[7];
    float* out = (float*)d_out;

    cudaFuncSetAttribute(gemm_mma_kernel,
                         cudaFuncAttributeMaxDynamicSharedMemorySize, GEMM_SMEM);
    cudaFuncSetAttribute(gemmY_kernel,
                         cudaFuncAttributeMaxDynamicSharedMemorySize, YSMEM);

    prep_kernel<<<(Hh*N2d + 255)/256, 256>>>(log_dt, C, lar, aim);
    wsplit_kernel<<<(2*Hh*Hh + 255)/256, 256>>>(Wm);
    powers_kernel<<<Hh, 256>>>(D);
    gemmS_kernel<<<dim3(NCOL/128, Hh), 256>>>(u);
    chain_kernel<<<(Bb*Hh)/8, 256>>>();
    gemmY_kernel<<<dim3(NCOL/128, Hh), 256, YSMEM>>>();
    dim3 grid(Ll/128, Hh/128, Bb);
    gemm_mma_kernel<<<grid, 512, GEMM_SMEM>>>(bias, out);
}